// round 4
// baseline (speedup 1.0000x reference)
#include <cuda_runtime.h>
#include <math.h>

#define BB 8
#define CC 128
#define NPIX (512*512)           // pixels per batch image
#define SPLIT 16                 // blocks per (b,c) plane in sum pass
#define CHUNK (NPIX/SPLIT)       // 16384 elements per block
#define PACKBLK 32               // k_pack blocks per batch
#define EPSV 1e-12f

typedef unsigned long long u64;

// ---- scratch (static device arrays; no allocations) ----
__device__ float  g_mf[BB*NPIX];            // 0.0/1.0 change mask (8.4 MB)
__device__ float  g_partC[SPLIT*BB*CC];     // partial masked sums
__device__ float  g_partT[SPLIT*BB*CC];     // partial total sums
__device__ int    g_cntPart[BB*PACKBLK];    // partial change counts
__device__ float2 g_dvec2[BB*CC];           // duplicated {d,d} pairs
__device__ float  g_valid[BB];

// ---- packed f32x2 helpers ----
__device__ __forceinline__ void fma2(u64 &d, u64 a, u64 b, u64 c) {
    asm("fma.rn.f32x2 %0, %1, %2, %3;" : "=l"(d) : "l"(a), "l"(b), "l"(c));
}
__device__ __forceinline__ void addp2(u64 &d, u64 a, u64 b) {
    asm("add.rn.f32x2 %0, %1, %2;" : "=l"(d) : "l"(a), "l"(b));
}
__device__ __forceinline__ float2 u2f(u64 v) {
    float2 r; asm("mov.b64 {%0,%1}, %2;" : "=f"(r.x), "=f"(r.y) : "l"(v)); return r;
}

// ---------------- pack gt -> float mask + partial counts ----------------
// grid: (PACKBLK, BB), 256 threads; each thread handles 32 pixels
__global__ void k_pack(const int* __restrict__ gt) {
    int b = blockIdx.y;
    int t = blockIdx.x * 256 + threadIdx.x;           // 32-pixel group index
    const int4* g4 = (const int4*)(gt + (size_t)b * NPIX) + (size_t)t * 8;
    float4*     m4 = (float4*)(g_mf + (size_t)b * NPIX) + (size_t)t * 8;
    int cnt = 0;
    #pragma unroll
    for (int i = 0; i < 8; i++) {
        int4 g = g4[i];
        float4 m;
        m.x = (g.x == 1) ? 1.f : 0.f;
        m.y = (g.y == 1) ? 1.f : 0.f;
        m.z = (g.z == 1) ? 1.f : 0.f;
        m.w = (g.w == 1) ? 1.f : 0.f;
        cnt += (g.x==1) + (g.y==1) + (g.z==1) + (g.w==1);
        m4[i] = m;
    }
    #pragma unroll
    for (int o = 16; o; o >>= 1) cnt += __shfl_down_sync(0xffffffffu, cnt, o);
    __shared__ int sc[8];
    int w = threadIdx.x >> 5;
    if ((threadIdx.x & 31) == 0) sc[w] = cnt;
    __syncthreads();
    if (threadIdx.x == 0) {
        int tc = 0;
        for (int i = 0; i < 8; i++) tc += sc[i];
        g_cntPart[b*PACKBLK + blockIdx.x] = tc;
    }
}

// ---------------- masked + total channel sums (packed f32x2) ----------------
// grid: (SPLIT, CC, BB), 256 threads
__global__ void k_sums(const float* __restrict__ fm) {
    int chunk = blockIdx.x, c = blockIdx.y, b = blockIdx.z;
    const ulonglong2* f2 = (const ulonglong2*)(fm + ((size_t)(b*CC + c)) * NPIX + (size_t)chunk * CHUNK);
    const ulonglong2* m2 = (const ulonglong2*)(g_mf + (size_t)b * NPIX + (size_t)chunk * CHUNK);
    u64 S0 = 0, S1 = 0, T0 = 0, T1 = 0;   // f32x2 accumulators (0.0,0.0)
    const int nvec = CHUNK / 4;           // 4096 16B vectors
    #pragma unroll 8
    for (int j = threadIdx.x; j < nvec; j += 256) {
        ulonglong2 v = f2[j];
        ulonglong2 m = m2[j];
        fma2(S0, v.x, m.x, S0);
        fma2(S1, v.y, m.y, S1);
        addp2(T0, T0, v.x);
        addp2(T1, T1, v.y);
    }
    float2 a = u2f(S0), bp = u2f(S1), tc0 = u2f(T0), tc1 = u2f(T1);
    float sc = a.x + a.y + bp.x + bp.y;
    float st = tc0.x + tc0.y + tc1.x + tc1.y;
    #pragma unroll
    for (int o = 16; o; o >>= 1) {
        sc += __shfl_down_sync(0xffffffffu, sc, o);
        st += __shfl_down_sync(0xffffffffu, st, o);
    }
    __shared__ float shc[8], sht[8];
    int w = threadIdx.x >> 5;
    if ((threadIdx.x & 31) == 0) { shc[w] = sc; sht[w] = st; }
    __syncthreads();
    if (threadIdx.x == 0) {
        float rc = 0.f, rt = 0.f;
        for (int i = 0; i < 8; i++) { rc += shc[i]; rt += sht[i]; }
        int idx = (chunk*BB + b)*CC + c;
        g_partC[idx] = rc;
        g_partT[idx] = rt;
    }
}

// ---------------- prototypes -> duplicated difference vector ----------------
// grid: BB blocks, CC threads
__global__ void k_proto() {
    int b = blockIdx.x, c = threadIdx.x;
    __shared__ float s_nc;
    if (c < 32) {
        int v = g_cntPart[b*PACKBLK + c];
        #pragma unroll
        for (int o = 16; o; o >>= 1) v += __shfl_down_sync(0xffffffffu, v, o);
        if (c == 0) s_nc = (float)v;
    }
    __syncthreads();
    float nc = s_nc;
    float nn = (float)NPIX - nc;

    float sC = 0.f, sT = 0.f;
    #pragma unroll
    for (int k = 0; k < SPLIT; k++) {
        int idx = (k*BB + b)*CC + c;
        sC += g_partC[idx];
        sT += g_partT[idx];
    }
    float pc = sC / fmaxf(nc, 1.f);
    float pn = (sT - sC) / fmaxf(nn, 1.f);

    float s1 = pc*pc, s2 = pn*pn;
    #pragma unroll
    for (int o = 16; o; o >>= 1) {
        s1 += __shfl_down_sync(0xffffffffu, s1, o);
        s2 += __shfl_down_sync(0xffffffffu, s2, o);
    }
    __shared__ float r1[4], r2[4];
    int w = c >> 5;
    if ((c & 31) == 0) { r1[w] = s1; r2[w] = s2; }
    __syncthreads();
    float t1 = r1[0] + r1[1] + r1[2] + r1[3];
    float t2 = r2[0] + r2[1] + r2[2] + r2[3];
    float npc = fmaxf(sqrtf(t1), EPSV);
    float npn = fmaxf(sqrtf(t2), EPSV);
    float d = pc / npc - pn / npn;
    g_dvec2[b*CC + c] = make_float2(d, d);
    if (c == 0) g_valid[b] = (nc > 0.f && nn > 0.f) ? 1.f : 0.f;
}

// ---------------- per-pixel similarity + exp (8 pixels/thread, f32x2) --------
// grid: (NPIX/2048, BB), 256 threads
__global__ void k_out(const float* __restrict__ fm, float* __restrict__ out) {
    int b = blockIdx.y;
    __shared__ u64  sd[CC];
    __shared__ float sval;
    if (threadIdx.x < CC) {
        float2 dv = g_dvec2[b*CC + threadIdx.x];
        u64 packed;
        asm("mov.b64 %0, {%1,%2};" : "=l"(packed) : "f"(dv.x), "f"(dv.y));
        sd[threadIdx.x] = packed;
    }
    if (threadIdx.x == 0) sval = g_valid[b];
    __syncthreads();

    int idx8 = blockIdx.x * 256 + threadIdx.x;        // 8-pixel group within plane
    const ulonglong2* fp = (const ulonglong2*)(fm + (size_t)b * CC * NPIX);
    size_t eA = (size_t)idx8 * 2;                     // two 16B vectors per thread
    size_t eB = eA + 1;
    const size_t plane = NPIX / 4;                    // 16B vectors per channel plane

    u64 s0=0, s1=0, s2=0, s3=0;
    u64 q0=0, q1=0, q2=0, q3=0;
    #pragma unroll 4
    for (int c = 0; c < CC; c++) {
        ulonglong2 vA = fp[(size_t)c * plane + eA];
        ulonglong2 vB = fp[(size_t)c * plane + eB];
        u64 d = sd[c];
        fma2(s0, vA.x, d, s0);  fma2(q0, vA.x, vA.x, q0);
        fma2(s1, vA.y, d, s1);  fma2(q1, vA.y, vA.y, q1);
        fma2(s2, vB.x, d, s2);  fma2(q2, vB.x, vB.x, q2);
        fma2(s3, vB.y, d, s3);  fma2(q3, vB.y, vB.y, q3);
    }

    const float4* mf4 = (const float4*)(g_mf + (size_t)b * NPIX);
    float4 mA = mf4[eA], mB = mf4[eB];
    float val = sval;

    float2 S0=u2f(s0), S1=u2f(s1), S2=u2f(s2), S3=u2f(s3);
    float2 Q0=u2f(q0), Q1=u2f(q1), Q2=u2f(q2), Q3=u2f(q3);

    float4 oA, oB;
    oA.x = val * __expf((2.f*mA.x - 1.f) * S0.x * rsqrtf(fmaxf(Q0.x, 1e-30f)));
    oA.y = val * __expf((2.f*mA.y - 1.f) * S0.y * rsqrtf(fmaxf(Q0.y, 1e-30f)));
    oA.z = val * __expf((2.f*mA.z - 1.f) * S1.x * rsqrtf(fmaxf(Q1.x, 1e-30f)));
    oA.w = val * __expf((2.f*mA.w - 1.f) * S1.y * rsqrtf(fmaxf(Q1.y, 1e-30f)));
    oB.x = val * __expf((2.f*mB.x - 1.f) * S2.x * rsqrtf(fmaxf(Q2.x, 1e-30f)));
    oB.y = val * __expf((2.f*mB.y - 1.f) * S2.y * rsqrtf(fmaxf(Q2.y, 1e-30f)));
    oB.z = val * __expf((2.f*mB.z - 1.f) * S3.x * rsqrtf(fmaxf(Q3.x, 1e-30f)));
    oB.w = val * __expf((2.f*mB.w - 1.f) * S3.y * rsqrtf(fmaxf(Q3.y, 1e-30f)));

    float4* o4 = (float4*)(out + (size_t)b * NPIX);
    o4[eA] = oA;
    o4[eB] = oB;
}

extern "C" void kernel_launch(void* const* d_in, const int* in_sizes, int n_in,
                              void* d_out, int out_size) {
    const float* fm = (const float*)d_in[0];
    const int*   gt = (const int*)d_in[1];
    float* out = (float*)d_out;

    {
        dim3 grid(PACKBLK, BB);
        k_pack<<<grid, 256>>>(gt);
    }
    {
        dim3 grid(SPLIT, CC, BB);
        k_sums<<<grid, 256>>>(fm);
    }
    k_proto<<<BB, CC>>>();
    {
        dim3 grid(NPIX/2048, BB);
        k_out<<<grid, 256>>>(fm, out);
    }
}

// round 5
// speedup vs baseline: 1.0040x; 1.0040x over previous
#include <cuda_runtime.h>
#include <math.h>

#define BB 8
#define CC 128
#define NPIX (512*512)           // pixels per batch image
#define SPLIT 16                 // blocks per (b,c) plane in sum pass
#define CHUNK (NPIX/SPLIT)       // 16384 elements per block
#define PACKBLK 32               // k_pack blocks per batch
#define EPSV 1e-12f

typedef unsigned long long u64;

// ---- scratch (static device arrays; no allocations) ----
__device__ float  g_mf[BB*NPIX];            // 0.0/1.0 change mask (8.4 MB)
__device__ float  g_partC[SPLIT*BB*CC];     // partial masked sums
__device__ float  g_partT[SPLIT*BB*CC];     // partial total sums
__device__ int    g_cntPart[BB*PACKBLK];    // partial change counts
__device__ float2 g_dvec2[BB*CC];           // duplicated {d,d} pairs
__device__ float  g_valid[BB];

// ---- packed f32x2 helpers ----
__device__ __forceinline__ void fma2(u64 &d, u64 a, u64 b, u64 c) {
    asm("fma.rn.f32x2 %0, %1, %2, %3;" : "=l"(d) : "l"(a), "l"(b), "l"(c));
}
__device__ __forceinline__ void addp2(u64 &d, u64 a, u64 b) {
    asm("add.rn.f32x2 %0, %1, %2;" : "=l"(d) : "l"(a), "l"(b));
}
__device__ __forceinline__ float2 u2f(u64 v) {
    float2 r; asm("mov.b64 {%0,%1}, %2;" : "=f"(r.x), "=f"(r.y) : "l"(v)); return r;
}

// ---------------- pack gt -> float mask + partial counts ----------------
// grid: (PACKBLK, BB), 256 threads; each thread handles 32 pixels
__global__ void k_pack(const int* __restrict__ gt) {
    int b = blockIdx.y;
    int t = blockIdx.x * 256 + threadIdx.x;           // 32-pixel group index
    const int4* g4 = (const int4*)(gt + (size_t)b * NPIX) + (size_t)t * 8;
    float4*     m4 = (float4*)(g_mf + (size_t)b * NPIX) + (size_t)t * 8;
    int cnt = 0;
    #pragma unroll
    for (int i = 0; i < 8; i++) {
        int4 g = g4[i];
        float4 m;
        m.x = (g.x == 1) ? 1.f : 0.f;
        m.y = (g.y == 1) ? 1.f : 0.f;
        m.z = (g.z == 1) ? 1.f : 0.f;
        m.w = (g.w == 1) ? 1.f : 0.f;
        cnt += (g.x==1) + (g.y==1) + (g.z==1) + (g.w==1);
        m4[i] = m;
    }
    #pragma unroll
    for (int o = 16; o; o >>= 1) cnt += __shfl_down_sync(0xffffffffu, cnt, o);
    __shared__ int sc[8];
    int w = threadIdx.x >> 5;
    if ((threadIdx.x & 31) == 0) sc[w] = cnt;
    __syncthreads();
    if (threadIdx.x == 0) {
        int tc = 0;
        for (int i = 0; i < 8; i++) tc += sc[i];
        g_cntPart[b*PACKBLK + blockIdx.x] = tc;
    }
}

// ---------------- masked + total channel sums (packed f32x2) ----------------
// grid: (SPLIT, CC, BB), 256 threads
__global__ void k_sums(const float* __restrict__ fm) {
    int chunk = blockIdx.x, c = blockIdx.y, b = blockIdx.z;
    const ulonglong2* f2 = (const ulonglong2*)(fm + ((size_t)(b*CC + c)) * NPIX + (size_t)chunk * CHUNK);
    const ulonglong2* m2 = (const ulonglong2*)(g_mf + (size_t)b * NPIX + (size_t)chunk * CHUNK);
    u64 S0 = 0, S1 = 0, T0 = 0, T1 = 0;   // f32x2 accumulators (0.0,0.0)
    const int nvec = CHUNK / 4;           // 4096 16B vectors
    #pragma unroll 8
    for (int j = threadIdx.x; j < nvec; j += 256) {
        ulonglong2 v = f2[j];
        ulonglong2 m = m2[j];
        fma2(S0, v.x, m.x, S0);
        fma2(S1, v.y, m.y, S1);
        addp2(T0, T0, v.x);
        addp2(T1, T1, v.y);
    }
    float2 a = u2f(S0), bp = u2f(S1), tc0 = u2f(T0), tc1 = u2f(T1);
    float sc = a.x + a.y + bp.x + bp.y;
    float st = tc0.x + tc0.y + tc1.x + tc1.y;
    #pragma unroll
    for (int o = 16; o; o >>= 1) {
        sc += __shfl_down_sync(0xffffffffu, sc, o);
        st += __shfl_down_sync(0xffffffffu, st, o);
    }
    __shared__ float shc[8], sht[8];
    int w = threadIdx.x >> 5;
    if ((threadIdx.x & 31) == 0) { shc[w] = sc; sht[w] = st; }
    __syncthreads();
    if (threadIdx.x == 0) {
        float rc = 0.f, rt = 0.f;
        for (int i = 0; i < 8; i++) { rc += shc[i]; rt += sht[i]; }
        int idx = (chunk*BB + b)*CC + c;
        g_partC[idx] = rc;
        g_partT[idx] = rt;
    }
}

// ---------------- prototypes -> duplicated difference vector ----------------
// grid: BB blocks, CC threads
__global__ void k_proto() {
    int b = blockIdx.x, c = threadIdx.x;
    __shared__ float s_nc;
    if (c < 32) {
        int v = g_cntPart[b*PACKBLK + c];
        #pragma unroll
        for (int o = 16; o; o >>= 1) v += __shfl_down_sync(0xffffffffu, v, o);
        if (c == 0) s_nc = (float)v;
    }
    __syncthreads();
    float nc = s_nc;
    float nn = (float)NPIX - nc;

    float sC = 0.f, sT = 0.f;
    #pragma unroll
    for (int k = 0; k < SPLIT; k++) {
        int idx = (k*BB + b)*CC + c;
        sC += g_partC[idx];
        sT += g_partT[idx];
    }
    float pc = sC / fmaxf(nc, 1.f);
    float pn = (sT - sC) / fmaxf(nn, 1.f);

    float s1 = pc*pc, s2 = pn*pn;
    #pragma unroll
    for (int o = 16; o; o >>= 1) {
        s1 += __shfl_down_sync(0xffffffffu, s1, o);
        s2 += __shfl_down_sync(0xffffffffu, s2, o);
    }
    __shared__ float r1[4], r2[4];
    int w = c >> 5;
    if ((c & 31) == 0) { r1[w] = s1; r2[w] = s2; }
    __syncthreads();
    float t1 = r1[0] + r1[1] + r1[2] + r1[3];
    float t2 = r2[0] + r2[1] + r2[2] + r2[3];
    float npc = fmaxf(sqrtf(t1), EPSV);
    float npn = fmaxf(sqrtf(t2), EPSV);
    float d = pc / npc - pn / npn;
    g_dvec2[b*CC + c] = make_float2(d, d);
    if (c == 0) g_valid[b] = (nc > 0.f && nn > 0.f) ? 1.f : 0.f;
}

// ---------------- per-pixel similarity + exp (8 pixels/thread, f32x2) --------
// grid: (NPIX/2048, BB), 256 threads
__global__ void k_out(const float* __restrict__ fm, float* __restrict__ out) {
    int b = blockIdx.y;
    __shared__ u64  sd[CC];
    __shared__ float sval;
    if (threadIdx.x < CC) {
        float2 dv = g_dvec2[b*CC + threadIdx.x];
        u64 packed;
        asm("mov.b64 %0, {%1,%2};" : "=l"(packed) : "f"(dv.x), "f"(dv.y));
        sd[threadIdx.x] = packed;
    }
    if (threadIdx.x == 0) sval = g_valid[b];
    __syncthreads();

    int idx8 = blockIdx.x * 256 + threadIdx.x;        // 8-pixel group within plane
    const ulonglong2* fp = (const ulonglong2*)(fm + (size_t)b * CC * NPIX);
    size_t eA = (size_t)idx8 * 2;                     // two 16B vectors per thread
    size_t eB = eA + 1;
    const size_t plane = NPIX / 4;                    // 16B vectors per channel plane

    u64 s0=0, s1=0, s2=0, s3=0;
    u64 q0=0, q1=0, q2=0, q3=0;
    #pragma unroll 4
    for (int c = 0; c < CC; c++) {
        ulonglong2 vA = fp[(size_t)c * plane + eA];
        ulonglong2 vB = fp[(size_t)c * plane + eB];
        u64 d = sd[c];
        fma2(s0, vA.x, d, s0);  fma2(q0, vA.x, vA.x, q0);
        fma2(s1, vA.y, d, s1);  fma2(q1, vA.y, vA.y, q1);
        fma2(s2, vB.x, d, s2);  fma2(q2, vB.x, vB.x, q2);
        fma2(s3, vB.y, d, s3);  fma2(q3, vB.y, vB.y, q3);
    }

    const float4* mf4 = (const float4*)(g_mf + (size_t)b * NPIX);
    float4 mA = mf4[eA], mB = mf4[eB];
    float val = sval;

    float2 S0=u2f(s0), S1=u2f(s1), S2=u2f(s2), S3=u2f(s3);
    float2 Q0=u2f(q0), Q1=u2f(q1), Q2=u2f(q2), Q3=u2f(q3);

    float4 oA, oB;
    oA.x = val * __expf((2.f*mA.x - 1.f) * S0.x * rsqrtf(fmaxf(Q0.x, 1e-30f)));
    oA.y = val * __expf((2.f*mA.y - 1.f) * S0.y * rsqrtf(fmaxf(Q0.y, 1e-30f)));
    oA.z = val * __expf((2.f*mA.z - 1.f) * S1.x * rsqrtf(fmaxf(Q1.x, 1e-30f)));
    oA.w = val * __expf((2.f*mA.w - 1.f) * S1.y * rsqrtf(fmaxf(Q1.y, 1e-30f)));
    oB.x = val * __expf((2.f*mB.x - 1.f) * S2.x * rsqrtf(fmaxf(Q2.x, 1e-30f)));
    oB.y = val * __expf((2.f*mB.y - 1.f) * S2.y * rsqrtf(fmaxf(Q2.y, 1e-30f)));
    oB.z = val * __expf((2.f*mB.z - 1.f) * S3.x * rsqrtf(fmaxf(Q3.x, 1e-30f)));
    oB.w = val * __expf((2.f*mB.w - 1.f) * S3.y * rsqrtf(fmaxf(Q3.y, 1e-30f)));

    float4* o4 = (float4*)(out + (size_t)b * NPIX);
    o4[eA] = oA;
    o4[eB] = oB;
}

extern "C" void kernel_launch(void* const* d_in, const int* in_sizes, int n_in,
                              void* d_out, int out_size) {
    const float* fm = (const float*)d_in[0];
    const int*   gt = (const int*)d_in[1];
    float* out = (float*)d_out;

    {
        dim3 grid(PACKBLK, BB);
        k_pack<<<grid, 256>>>(gt);
    }
    {
        dim3 grid(SPLIT, CC, BB);
        k_sums<<<grid, 256>>>(fm);
    }
    k_proto<<<BB, CC>>>();
    {
        dim3 grid(NPIX/2048, BB);
        k_out<<<grid, 256>>>(fm, out);
    }
}

// round 6
// speedup vs baseline: 1.1998x; 1.1951x over previous
#include <cuda_runtime.h>
#include <math.h>

#define BB 8
#define CC 128
#define NPIX (512*512)           // pixels per batch image
#define SPLIT 16                 // blocks per (b,c) plane in sum pass
#define CHUNK (NPIX/SPLIT)       // 16384 elements per block
#define EPSV 1e-12f

// ---- scratch (static device arrays; no allocations) ----
__device__ float  g_partC[SPLIT*BB*CC];   // partial masked sums
__device__ float  g_partT[SPLIT*BB*CC];   // partial total sums
__device__ int    g_cntPart[BB*SPLIT];    // partial change counts
__device__ float  g_dvec[BB*CC];          // prototype difference vector
__device__ float  g_valid[BB];

// ---------------- masked + total channel sums (+ counts on c==0) -------------
// grid: (SPLIT, CC, BB), 256 threads. Contiguous 64KB fm chunk per block.
__global__ void __launch_bounds__(256, 8)
k_sums(const float* __restrict__ fm, const int* __restrict__ gt) {
    int chunk = blockIdx.x, c = blockIdx.y, b = blockIdx.z;
    const float4* f4 = (const float4*)(fm + ((size_t)(b*CC + c)) * NPIX + (size_t)chunk * CHUNK);
    const int4*   g4 = (const int4*)(gt + (size_t)b * NPIX + (size_t)chunk * CHUNK);
    float sc = 0.f, st = 0.f;
    int cnt = 0;
    const int nvec = CHUNK / 4;  // 4096 float4s
    #pragma unroll 4
    for (int j = threadIdx.x; j < nvec; j += 256) {
        float4 v = __ldcs(f4 + j);      // evict-first: pure stream
        int4   g = __ldg(g4 + j);       // L2-resident, reused by 128 blocks
        sc += (g.x ? v.x : 0.f) + (g.y ? v.y : 0.f) + (g.z ? v.z : 0.f) + (g.w ? v.w : 0.f);
        st += v.x + v.y + v.z + v.w;
        if (c == 0) cnt += g.x + g.y + g.z + g.w;   // gt in {0,1}
    }
    #pragma unroll
    for (int o = 16; o; o >>= 1) {
        sc += __shfl_down_sync(0xffffffffu, sc, o);
        st += __shfl_down_sync(0xffffffffu, st, o);
        if (c == 0) cnt += __shfl_down_sync(0xffffffffu, cnt, o);
    }
    __shared__ float shc[8], sht[8];
    __shared__ int   shn[8];
    int w = threadIdx.x >> 5;
    if ((threadIdx.x & 31) == 0) { shc[w] = sc; sht[w] = st; shn[w] = cnt; }
    __syncthreads();
    if (threadIdx.x == 0) {
        float rc = 0.f, rt = 0.f;
        int   rn = 0;
        #pragma unroll
        for (int i = 0; i < 8; i++) { rc += shc[i]; rt += sht[i]; rn += shn[i]; }
        int idx = (chunk*BB + b)*CC + c;
        g_partC[idx] = rc;
        g_partT[idx] = rt;
        if (c == 0) g_cntPart[b*SPLIT + chunk] = rn;
    }
}

// ---------------- prototypes -> difference vector ----------------
// grid: BB blocks, CC threads
__global__ void k_proto() {
    int b = blockIdx.x, c = threadIdx.x;
    __shared__ float s_nc;
    if (c < 32) {
        int v = (c < SPLIT) ? g_cntPart[b*SPLIT + c] : 0;
        #pragma unroll
        for (int o = 16; o; o >>= 1) v += __shfl_down_sync(0xffffffffu, v, o);
        if (c == 0) s_nc = (float)v;
    }
    __syncthreads();
    float nc = s_nc;
    float nn = (float)NPIX - nc;

    float sC = 0.f, sT = 0.f;
    #pragma unroll
    for (int k = 0; k < SPLIT; k++) {
        int idx = (k*BB + b)*CC + c;
        sC += g_partC[idx];
        sT += g_partT[idx];
    }
    float pc = sC / fmaxf(nc, 1.f);
    float pn = (sT - sC) / fmaxf(nn, 1.f);

    float s1 = pc*pc, s2 = pn*pn;
    #pragma unroll
    for (int o = 16; o; o >>= 1) {
        s1 += __shfl_down_sync(0xffffffffu, s1, o);
        s2 += __shfl_down_sync(0xffffffffu, s2, o);
    }
    __shared__ float r1[4], r2[4];
    int w = c >> 5;
    if ((c & 31) == 0) { r1[w] = s1; r2[w] = s2; }
    __syncthreads();
    float t1 = r1[0] + r1[1] + r1[2] + r1[3];
    float t2 = r2[0] + r2[1] + r2[2] + r2[3];
    float npc = fmaxf(sqrtf(t1), EPSV);
    float npn = fmaxf(sqrtf(t2), EPSV);
    g_dvec[b*CC + c] = pc / npc - pn / npn;
    if (c == 0) g_valid[b] = (nc > 0.f && nn > 0.f) ? 1.f : 0.f;
}

// ---------------- per-pixel similarity + exp ----------------
// grid: (NPIX/2048, BB), 512 threads, 4 pixels (one float4) per thread.
__global__ void __launch_bounds__(512, 4)
k_out(const float* __restrict__ fm, const int* __restrict__ gt,
      float* __restrict__ out) {
    int b = blockIdx.y;
    __shared__ float sd[CC];
    __shared__ float sval;
    if (threadIdx.x < CC) sd[threadIdx.x] = g_dvec[b*CC + threadIdx.x];
    if (threadIdx.x == 0) sval = g_valid[b];
    __syncthreads();

    int base = blockIdx.x * 512 + threadIdx.x;     // float4 index within plane
    const float4* f4 = (const float4*)(fm + (size_t)b * CC * NPIX);
    const size_t plane = NPIX / 4;                 // float4s per channel plane

    float4 s = {0.f,0.f,0.f,0.f};
    float4 q = {0.f,0.f,0.f,0.f};
    #pragma unroll 8
    for (int c = 0; c < CC; c++) {
        float4 v = __ldcs(f4 + (size_t)c * plane + base);
        float dc = sd[c];
        s.x = fmaf(v.x, dc, s.x);  q.x = fmaf(v.x, v.x, q.x);
        s.y = fmaf(v.y, dc, s.y);  q.y = fmaf(v.y, v.y, q.y);
        s.z = fmaf(v.z, dc, s.z);  q.z = fmaf(v.z, v.z, q.z);
        s.w = fmaf(v.w, dc, s.w);  q.w = fmaf(v.w, v.w, q.w);
    }
    int4 g = __ldg((const int4*)(gt + (size_t)b * NPIX) + base);
    float val = sval;
    float4 o;
    o.x = val * __expf((g.x ? 1.f : -1.f) * s.x * rsqrtf(fmaxf(q.x, 1e-30f)));
    o.y = val * __expf((g.y ? 1.f : -1.f) * s.y * rsqrtf(fmaxf(q.y, 1e-30f)));
    o.z = val * __expf((g.z ? 1.f : -1.f) * s.z * rsqrtf(fmaxf(q.z, 1e-30f)));
    o.w = val * __expf((g.w ? 1.f : -1.f) * s.w * rsqrtf(fmaxf(q.w, 1e-30f)));
    ((float4*)(out + (size_t)b * NPIX))[base] = o;
}

extern "C" void kernel_launch(void* const* d_in, const int* in_sizes, int n_in,
                              void* d_out, int out_size) {
    const float* fm = (const float*)d_in[0];
    const int*   gt = (const int*)d_in[1];
    float* out = (float*)d_out;

    {
        dim3 grid(SPLIT, CC, BB);
        k_sums<<<grid, 256>>>(fm, gt);
    }
    k_proto<<<BB, CC>>>();
    {
        dim3 grid(NPIX/2048, BB);
        k_out<<<grid, 512>>>(fm, gt, out);
    }
}